// round 6
// baseline (speedup 1.0000x reference)
#include <cuda_runtime.h>
#include <cuda_bf16.h>
#include <cstddef>

#define S_LEN 2048
#define B_DIM 64
#define I_DIM 512
#define H_DIM 512
#define BH (B_DIM * H_DIM)          // 32768
#define GX_COLS 1024                // z gates [0,512), n gates [512,1024)

// Scratch: gx[t][b][g], g in 0..1023 maps to weight rows 512+g. 512 MB.
__device__ float g_gx[(size_t)S_LEN * B_DIM * GX_COLS];
// Per-CTA step flags. Monotone forever; each launch reads its own flag as
// fbase and compares (flag - fbase) — correct across graph replays with no
// reset step.
__device__ int g_flag[128];

typedef unsigned long long ull;

__device__ __forceinline__ ull fma2(ull a, ull b, ull c) {
    ull d;
    asm("fma.rn.f32x2 %0, %1, %2, %3;" : "=l"(d) : "l"(a), "l"(b), "l"(c));
    return d;
}
__device__ __forceinline__ float sum2(ull u) {
    float lo, hi;
    asm("mov.b64 {%0,%1}, %2;" : "=f"(lo), "=f"(hi) : "l"(u));
    return lo + hi;
}
__device__ __forceinline__ void st_rel(int* p, int v) {
    asm volatile("st.release.gpu.global.b32 [%0], %1;" :: "l"(p), "r"(v) : "memory");
}
__device__ __forceinline__ int ld_acq(const int* p) {
    int v;
    asm volatile("ld.acquire.gpu.global.b32 %0, [%1];" : "=r"(v) : "l"(p) : "memory");
    return v;
}

// ---------------------------------------------------------------------------
// Kernel 1: gx = x @ Wih[512:1536]^T + (bias_ih + bias_hh)[512:1536]
// M=131072, N=1024, K=512. BM=BN=128, BK=16, 256 threads, 8x8 f32x2 tile.
// (unchanged — proven at R2..R4)
// ---------------------------------------------------------------------------
__global__ void __launch_bounds__(256, 1)
gx_gemm(const float* __restrict__ x, const float* __restrict__ wih,
        const float* __restrict__ bih, const float* __restrict__ bhh) {
    __shared__ ull As2[8 * 130];
    __shared__ ull Bs2[8 * 130];

    const int tid = threadIdx.x;
    const int tx = tid & 15;
    const int ty = tid >> 4;
    const int n0 = blockIdx.x * 128;
    const size_t m0 = (size_t)blockIdx.y * 128;
    const int r = tid >> 1;
    const int half = tid & 1;
    const int kp0 = half * 4;

    float bz[8];
#pragma unroll
    for (int j = 0; j < 8; j++) {
        int n = n0 + tx + 16 * j;
        bz[j] = bih[512 + n] + bhh[512 + n];
    }

    ull acc[8][8];
#pragma unroll
    for (int i = 0; i < 8; i++)
#pragma unroll
        for (int j = 0; j < 8; j++) acc[i][j] = 0ull;

    const float* arow = x + (m0 + r) * 512 + half * 8;
    const float* brow = wih + (size_t)(512 + n0 + r) * 512 + half * 8;

    ulonglong2 A0 = *(const ulonglong2*)(arow);
    ulonglong2 A1 = *(const ulonglong2*)(arow + 4);
    ulonglong2 B0 = *(const ulonglong2*)(brow);
    ulonglong2 B1 = *(const ulonglong2*)(brow + 4);

    for (int kt = 0; kt < 32; kt++) {
        As2[(kp0 + 0) * 130 + r] = A0.x;
        As2[(kp0 + 1) * 130 + r] = A0.y;
        As2[(kp0 + 2) * 130 + r] = A1.x;
        As2[(kp0 + 3) * 130 + r] = A1.y;
        Bs2[(kp0 + 0) * 130 + r] = B0.x;
        Bs2[(kp0 + 1) * 130 + r] = B0.y;
        Bs2[(kp0 + 2) * 130 + r] = B1.x;
        Bs2[(kp0 + 3) * 130 + r] = B1.y;
        __syncthreads();
        if (kt < 31) {
            int ko = (kt + 1) * 16;
            A0 = *(const ulonglong2*)(arow + ko);
            A1 = *(const ulonglong2*)(arow + ko + 4);
            B0 = *(const ulonglong2*)(brow + ko);
            B1 = *(const ulonglong2*)(brow + ko + 4);
        }
#pragma unroll
        for (int kp = 0; kp < 8; kp++) {
            ull av[8], bv[8];
            const ulonglong2* ap = (const ulonglong2*)&As2[kp * 130 + ty * 8];
#pragma unroll
            for (int i2 = 0; i2 < 4; i2++) {
                ulonglong2 t2 = ap[i2];
                av[i2 * 2] = t2.x;
                av[i2 * 2 + 1] = t2.y;
            }
#pragma unroll
            for (int j = 0; j < 8; j++) bv[j] = Bs2[kp * 130 + tx + 16 * j];
#pragma unroll
            for (int i = 0; i < 8; i++)
#pragma unroll
                for (int j = 0; j < 8; j++) acc[i][j] = fma2(av[i], bv[j], acc[i][j]);
        }
        __syncthreads();
    }

#pragma unroll
    for (int i = 0; i < 8; i++) {
        float* orow = g_gx + (m0 + ty * 8 + i) * (size_t)GX_COLS + n0 + tx;
#pragma unroll
        for (int j = 0; j < 8; j++) orow[16 * j] = sum2(acc[i][j]) + bz[j];
    }
}

// ---------------------------------------------------------------------------
// Kernel 2: recurrence. 128 CTAs = 8 groups x 16 CTAs; group g owns batches
// 8g..8g+7, CTA c owns h-dims [32c, 32c+32). 512 threads = 16 warps; warp w
// owns hd pair {hd0+2w, hd0+2w+1}; lane owns k slice [16*lane, 16*lane+16).
// Weights: 4 rows (z0,z1,n0,n1) x 16 k = 64 floats in registers.
// Per step: for each of 8 batches, 32 fma2 then a 5-round 32-lane butterfly;
// lane 2b+hdbit keeps the (z,n) sums of (batch b, hd0+2w+hdbit). Lanes 0..15
// each do exactly one h-update. h in SMEM as [b][j][lane] (j = float4 index
// within the lane's 16-k slice), pad 34 -> conflict-free LDS/STS.128.
// ---------------------------------------------------------------------------
__global__ void __launch_bounds__(512, 1)
rec_kernel(const float* __restrict__ h0, const float* __restrict__ whh,
           float* __restrict__ out) {
    __shared__ float4 h4s[8][4][34];   // k = lane*16 + j*4 + e

    const int tid = threadIdx.x;
    const int bx = blockIdx.x;
    const int grp = bx >> 4;
    const int gb = grp * 8;
    const int hd0 = (bx & 15) * 32;
    const int w = tid >> 5;
    const int lane = tid & 31;

    // Per-launch flag base (own flag; all group flags are equal at launch).
    const int fbase = g_flag[bx];

    // Step-invariant weights: rows z(2w), z(2w+1), n(2w), n(2w+1), 16 k each.
    ull wz0[8], wz1[8], wn0[8], wn1[8];
    {
        const float* rz0 = whh + (size_t)(512 + hd0 + 2 * w) * 512 + lane * 16;
        const float* rz1 = rz0 + 512;
        const float* rn0 = whh + (size_t)(1024 + hd0 + 2 * w) * 512 + lane * 16;
        const float* rn1 = rn0 + 512;
#pragma unroll
        for (int q = 0; q < 4; q++) {
            ulonglong2 a = ((const ulonglong2*)rz0)[q];
            wz0[2 * q] = a.x; wz0[2 * q + 1] = a.y;
            ulonglong2 b = ((const ulonglong2*)rz1)[q];
            wz1[2 * q] = b.x; wz1[2 * q + 1] = b.y;
            ulonglong2 cc = ((const ulonglong2*)rn0)[q];
            wn0[2 * q] = cc.x; wn0[2 * q + 1] = cc.y;
            ulonglong2 dd = ((const ulonglong2*)rn1)[q];
            wn1[2 * q] = dd.x; wn1[2 * q + 1] = dd.y;
        }
    }

    // Epilogue cell for lanes 0..15: batch eb, dim ghd.
    const int eb = (lane >> 1) & 7;
    const int ghd = hd0 + 2 * w + (lane & 1);
    const bool ep = (lane < 16);
    const float* gxp = g_gx + (size_t)(gb + eb) * GX_COLS + ghd;
    float* outp = out + (size_t)(gb + eb) * 512 + ghd;
    // h_old location in SMEM for the epilogue cell:
    const int ef4 = ghd >> 2;
    const int ej = ef4 & 3, el = ef4 >> 2, ee = ghd & 3;

    // Stage h(-1) = h_0.
#pragma unroll
    for (int it = 0; it < 2; it++) {
        int idx = tid + it * 512;
        int b = idx >> 7, f = idx & 127;
        h4s[b][f & 3][f >> 2] = __ldcg((const float4*)(h0 + (size_t)(gb + b) * 512) + f);
    }
    __syncthreads();

    for (int t = 0; t < S_LEN; t++) {
        // Prefetch gx cell for this lane (hidden behind the fma block).
        float pgz = 0.f, pgn = 0.f;
        if (ep) {
            const float* g = gxp + (size_t)t * (B_DIM * GX_COLS);
            pgz = __ldcg(g);
            pgn = __ldcg(g + 512);
        }

        float my_z = 0.f, my_n = 0.f;
#pragma unroll
        for (int b = 0; b < 8; b++) {
            ull az0 = 0, az1 = 0, an0 = 0, an1 = 0;
#pragma unroll
            for (int j = 0; j < 4; j++) {
                ulonglong2 h2 = *(const ulonglong2*)&h4s[b][j][lane];
                az0 = fma2(wz0[2 * j], h2.x, az0);
                az0 = fma2(wz0[2 * j + 1], h2.y, az0);
                az1 = fma2(wz1[2 * j], h2.x, az1);
                az1 = fma2(wz1[2 * j + 1], h2.y, az1);
                an0 = fma2(wn0[2 * j], h2.x, an0);
                an0 = fma2(wn0[2 * j + 1], h2.y, an0);
                an1 = fma2(wn1[2 * j], h2.x, an1);
                an1 = fma2(wn1[2 * j + 1], h2.y, an1);
            }
            float vz0 = sum2(az0), vz1 = sum2(az1);
            float vn0 = sum2(an0), vn1 = sum2(an1);
#pragma unroll
            for (int m = 1; m < 32; m <<= 1) {
                vz0 += __shfl_xor_sync(0xffffffffu, vz0, m);
                vz1 += __shfl_xor_sync(0xffffffffu, vz1, m);
                vn0 += __shfl_xor_sync(0xffffffffu, vn0, m);
                vn1 += __shfl_xor_sync(0xffffffffu, vn1, m);
            }
            if ((lane >> 1) == b) {
                my_z = (lane & 1) ? vz1 : vz0;
                my_n = (lane & 1) ? vn1 : vn0;
            }
        }

        // Epilogue: lanes 0..15 update one (batch, dim) cell.
        if (ep) {
            float h_old = ((const float*)&h4s[eb][ej][el])[ee];
            float z = 1.0f / (1.0f + expf(-(pgz + my_z)));
            float nn = tanhf(pgn + my_n);
            float hv = h_old + z * (nn - h_old);
            __stcg(outp + (size_t)t * BH, hv);
            if (t == S_LEN - 1)
                __stcg(outp + (size_t)S_LEN * BH, hv);
        }

        // Group barrier: flags monotone, compared relative to fbase.
        __syncthreads();
        if (tid == 0) st_rel(&g_flag[bx], fbase + t + 1);
        if (tid < 16) {
            const int* fl = &g_flag[grp * 16 + tid];
            while (ld_acq(fl) - fbase < t + 1) __nanosleep(20);
        }
        __syncthreads();

        // Restage h[t] from out (L2) into SMEM.
#pragma unroll
        for (int it = 0; it < 2; it++) {
            int idx = tid + it * 512;
            int b = idx >> 7, f = idx & 127;
            h4s[b][f & 3][f >> 2] =
                __ldcg((const float4*)(out + (size_t)t * BH + (size_t)(gb + b) * 512) + f);
        }
        __syncthreads();
    }
}

extern "C" void kernel_launch(void* const* d_in, const int* in_sizes, int n_in,
                              void* d_out, int out_size) {
    const float* x   = (const float*)d_in[0];  // (S, B, I)
    const float* h0  = (const float*)d_in[1];  // (1, B, H)
    const float* wih = (const float*)d_in[2];  // (3H, I)
    const float* whh = (const float*)d_in[3];  // (3H, H)
    const float* bih = (const float*)d_in[4];  // (3H,)
    const float* bhh = (const float*)d_in[5];  // (3H,)
    float* out = (float*)d_out;                // (1,S,B,H) then (1,B,H)

    dim3 ggrid(8, 1024);
    gx_gemm<<<ggrid, 256>>>(x, wih, bih, bhh);
    rec_kernel<<<128, 512>>>(h0, whh, out);
}

// round 7
// speedup vs baseline: 1.4098x; 1.4098x over previous
#include <cuda_runtime.h>
#include <cuda_bf16.h>
#include <cstddef>

#define S_LEN 2048
#define B_DIM 64
#define I_DIM 512
#define H_DIM 512
#define BH (B_DIM * H_DIM)          // 32768
#define GX_COLS 1024                // z gates [0,512), n gates [512,1024)

// Scratch: gx[t][b][g], g in 0..1023 maps to weight rows 512+g. 512 MB.
__device__ float g_gx[(size_t)S_LEN * B_DIM * GX_COLS];
// Sense-reversing group barrier state (8 groups). Returns to {0,0} after the
// even number (2048) of flips each launch -> replay-safe.
__device__ int g_cnt[8];
__device__ int g_sense[8];

typedef unsigned long long ull;

__device__ __forceinline__ ull fma2(ull a, ull b, ull c) {
    ull d;
    asm("fma.rn.f32x2 %0, %1, %2, %3;" : "=l"(d) : "l"(a), "l"(b), "l"(c));
    return d;
}
__device__ __forceinline__ float sum2(ull u) {
    float lo, hi;
    asm("mov.b64 {%0,%1}, %2;" : "=f"(lo), "=f"(hi) : "l"(u));
    return lo + hi;
}
__device__ __forceinline__ void st_rel(int* p, int v) {
    asm volatile("st.release.gpu.global.b32 [%0], %1;" :: "l"(p), "r"(v) : "memory");
}
__device__ __forceinline__ int ld_acq(const int* p) {
    int v;
    asm volatile("ld.acquire.gpu.global.b32 %0, [%1];" : "=r"(v) : "l"(p) : "memory");
    return v;
}
// Fast gates: MUFU-based, ~1e-7 abs error, saturate correctly at +-inf.
__device__ __forceinline__ float fsig(float x) {
    return __fdividef(1.0f, 1.0f + __expf(-x));
}
__device__ __forceinline__ float ftanh(float x) {
    return 1.0f - __fdividef(2.0f, __expf(2.0f * x) + 1.0f);
}

// ---------------------------------------------------------------------------
// Kernel 1: gx = x @ Wih[512:1536]^T + (bias_ih + bias_hh)[512:1536]
// M=131072, N=1024, K=512. BM=BN=128, BK=16, 256 threads, 8x8 f32x2 tile.
// (unchanged — proven R2..R5)
// ---------------------------------------------------------------------------
__global__ void __launch_bounds__(256, 1)
gx_gemm(const float* __restrict__ x, const float* __restrict__ wih,
        const float* __restrict__ bih, const float* __restrict__ bhh) {
    __shared__ ull As2[8 * 130];
    __shared__ ull Bs2[8 * 130];

    const int tid = threadIdx.x;
    const int tx = tid & 15;
    const int ty = tid >> 4;
    const int n0 = blockIdx.x * 128;
    const size_t m0 = (size_t)blockIdx.y * 128;
    const int r = tid >> 1;
    const int half = tid & 1;
    const int kp0 = half * 4;

    float bz[8];
#pragma unroll
    for (int j = 0; j < 8; j++) {
        int n = n0 + tx + 16 * j;
        bz[j] = bih[512 + n] + bhh[512 + n];
    }

    ull acc[8][8];
#pragma unroll
    for (int i = 0; i < 8; i++)
#pragma unroll
        for (int j = 0; j < 8; j++) acc[i][j] = 0ull;

    const float* arow = x + (m0 + r) * 512 + half * 8;
    const float* brow = wih + (size_t)(512 + n0 + r) * 512 + half * 8;

    ulonglong2 A0 = *(const ulonglong2*)(arow);
    ulonglong2 A1 = *(const ulonglong2*)(arow + 4);
    ulonglong2 B0 = *(const ulonglong2*)(brow);
    ulonglong2 B1 = *(const ulonglong2*)(brow + 4);

    for (int kt = 0; kt < 32; kt++) {
        As2[(kp0 + 0) * 130 + r] = A0.x;
        As2[(kp0 + 1) * 130 + r] = A0.y;
        As2[(kp0 + 2) * 130 + r] = A1.x;
        As2[(kp0 + 3) * 130 + r] = A1.y;
        Bs2[(kp0 + 0) * 130 + r] = B0.x;
        Bs2[(kp0 + 1) * 130 + r] = B0.y;
        Bs2[(kp0 + 2) * 130 + r] = B1.x;
        Bs2[(kp0 + 3) * 130 + r] = B1.y;
        __syncthreads();
        if (kt < 31) {
            int ko = (kt + 1) * 16;
            A0 = *(const ulonglong2*)(arow + ko);
            A1 = *(const ulonglong2*)(arow + ko + 4);
            B0 = *(const ulonglong2*)(brow + ko);
            B1 = *(const ulonglong2*)(brow + ko + 4);
        }
#pragma unroll
        for (int kp = 0; kp < 8; kp++) {
            ull av[8], bv[8];
            const ulonglong2* ap = (const ulonglong2*)&As2[kp * 130 + ty * 8];
#pragma unroll
            for (int i2 = 0; i2 < 4; i2++) {
                ulonglong2 t2 = ap[i2];
                av[i2 * 2] = t2.x;
                av[i2 * 2 + 1] = t2.y;
            }
#pragma unroll
            for (int j = 0; j < 8; j++) bv[j] = Bs2[kp * 130 + tx + 16 * j];
#pragma unroll
            for (int i = 0; i < 8; i++)
#pragma unroll
                for (int j = 0; j < 8; j++) acc[i][j] = fma2(av[i], bv[j], acc[i][j]);
        }
        __syncthreads();
    }

#pragma unroll
    for (int i = 0; i < 8; i++) {
        float* orow = g_gx + (m0 + ty * 8 + i) * (size_t)GX_COLS + n0 + tx;
#pragma unroll
        for (int j = 0; j < 8; j++) orow[16 * j] = sum2(acc[i][j]) + bz[j];
    }
}

// ---------------------------------------------------------------------------
// Kernel 2: recurrence — EXACT R2 structure (best measured: 6.4us/step).
// 128 CTAs = 8 groups x 16 CTAs; group g: batches 8g..8g+7; CTA c: h-dims
// [32c, 32c+32). 256 threads; thread (wid,lane): hdg = wid*2 + (lane>>4),
// kp = lane&15; owns rows {z0,z1,n0,n1} of hd pair {hd0+2hdg, +1} over k in
// [32kp, 32kp+32): 128 weight floats in registers, step-invariant.
// Changes vs R2: (1) tid0-only fence.acq_rel.gpu instead of all-thread
// __threadfence; (2) st.release / ld.acquire on the sense flag; (3) MUFU
// fast sigmoid/tanh in the epilogue.
// ---------------------------------------------------------------------------
__global__ void __launch_bounds__(256, 1)
rec_kernel(const float* __restrict__ h0, const float* __restrict__ whh,
           float* __restrict__ out) {
    __shared__ float4 h_s4[8][8][17];   // [b][q][kp] swizzled, k=(kp*8+q)*4+e

    const int tid = threadIdx.x;
    const int bx = blockIdx.x;
    const int grp = bx >> 4;
    const int gb = grp * 8;
    const int hd0 = (bx & 15) * 32;
    const int lane = tid & 31;
    const int wid = tid >> 5;
    const int kp = lane & 15;
    const int h1 = lane >> 4;
    const int hdg = wid * 2 + h1;
    const int hdp = hd0 + hdg * 2;      // this thread's hd pair base
    const bool isres = (kp == 0);

    // Step-invariant weights in registers (128 floats).
    ulonglong2 wz0[8], wz1[8], wn0[8], wn1[8];
    {
        const ulonglong2* pz0 = (const ulonglong2*)(whh + (size_t)(512 + hdp) * 512 + kp * 32);
        const ulonglong2* pz1 = (const ulonglong2*)(whh + (size_t)(513 + hdp) * 512 + kp * 32);
        const ulonglong2* pn0 = (const ulonglong2*)(whh + (size_t)(1024 + hdp) * 512 + kp * 32);
        const ulonglong2* pn1 = (const ulonglong2*)(whh + (size_t)(1025 + hdp) * 512 + kp * 32);
#pragma unroll
        for (int q = 0; q < 8; q++) {
            wz0[q] = pz0[q];
            wz1[q] = pz1[q];
            wn0[q] = pn0[q];
            wn1[q] = pn1[q];
        }
    }

    // Stage h(-1) = h_0 into swizzled SMEM.
    {
        int b = tid >> 5, rr = tid & 31;
        const float4* src = (const float4*)(h0 + (size_t)(gb + b) * 512);
#pragma unroll
        for (int j = 0; j < 4; j++) {
            int k4 = j * 32 + rr;
            h_s4[b][k4 & 7][k4 >> 3] = __ldcg(src + k4);
        }
    }
    __syncthreads();

    int sense = 0;

    for (int t = 0; t < S_LEN; t++) {
        // Prefetch gx[t] cells for this thread (hidden behind the fma block).
        float2 pgz[8], pgn[8];
        if (isres) {
            const float* gxt = g_gx + (size_t)t * B_DIM * GX_COLS;
#pragma unroll
            for (int b = 0; b < 8; b++) {
                pgz[b] = __ldcg((const float2*)(gxt + (size_t)(gb + b) * GX_COLS + hdp));
                pgn[b] = __ldcg((const float2*)(gxt + (size_t)(gb + b) * GX_COLS + 512 + hdp));
            }
        }

#pragma unroll
        for (int b = 0; b < 8; b++) {
            ull az0 = 0, az1 = 0, an0 = 0, an1 = 0;
#pragma unroll
            for (int q = 0; q < 8; q++) {
                ulonglong2 h2 = *(const ulonglong2*)&h_s4[b][q][kp];
                az0 = fma2(wz0[q].x, h2.x, az0);
                az0 = fma2(wz0[q].y, h2.y, az0);
                az1 = fma2(wz1[q].x, h2.x, az1);
                az1 = fma2(wz1[q].y, h2.y, az1);
                an0 = fma2(wn0[q].x, h2.x, an0);
                an0 = fma2(wn0[q].y, h2.y, an0);
                an1 = fma2(wn1[q].x, h2.x, an1);
                an1 = fma2(wn1[q].y, h2.y, an1);
            }
            float rz0 = sum2(az0), rz1 = sum2(az1);
            float rn0 = sum2(an0), rn1 = sum2(an1);
#pragma unroll
            for (int off = 1; off < 16; off <<= 1) {
                rz0 += __shfl_xor_sync(0xffffffffu, rz0, off);
                rz1 += __shfl_xor_sync(0xffffffffu, rz1, off);
                rn0 += __shfl_xor_sync(0xffffffffu, rn0, off);
                rn1 += __shfl_xor_sync(0xffffffffu, rn1, off);
            }
            if (isres) {
                int k4h = hdp >> 2;
                float4 ho4 = h_s4[b][k4h & 7][k4h >> 3];
                float ho0 = (hdp & 2) ? ho4.z : ho4.x;
                float ho1 = (hdp & 2) ? ho4.w : ho4.y;
                float z0 = fsig(pgz[b].x + rz0);
                float z1 = fsig(pgz[b].y + rz1);
                float n0v = ftanh(pgn[b].x + rn0);
                float n1v = ftanh(pgn[b].y + rn1);
                float2 hv;
                hv.x = ho0 + z0 * (n0v - ho0);
                hv.y = ho1 + z1 * (n1v - ho1);
                float* dst = out + (size_t)t * BH + (size_t)(gb + b) * 512 + hdp;
                *(float2*)dst = hv;
                if (t == S_LEN - 1) {
                    float* dn = out + (size_t)S_LEN * BH + (size_t)(gb + b) * 512 + hdp;
                    *(float2*)dn = hv;
                }
            }
        }

        // Group barrier. bar.sync orders all CTA threads' h stores before
        // tid0; tid0's gpu-scope fence + release publish them; pollers use
        // acquire so the post-barrier restage sees all h[t].
        __syncthreads();
        sense ^= 1;
        if (tid == 0) {
            asm volatile("fence.acq_rel.gpu;" ::: "memory");
            if (atomicAdd(&g_cnt[grp], 1) == 15) {
                g_cnt[grp] = 0;
                st_rel(&g_sense[grp], sense);
            } else {
                while (ld_acq(&g_sense[grp]) != sense) __nanosleep(32);
            }
        }
        __syncthreads();

        // Restage h[t] from out (L2) into swizzled SMEM.
        {
            int b = tid >> 5, rr = tid & 31;
            const float4* src = (const float4*)(out + (size_t)t * BH + (size_t)(gb + b) * 512);
#pragma unroll
            for (int j = 0; j < 4; j++) {
                int k4 = j * 32 + rr;
                h_s4[b][k4 & 7][k4 >> 3] = __ldcg(src + k4);
            }
        }
        __syncthreads();
    }
}

extern "C" void kernel_launch(void* const* d_in, const int* in_sizes, int n_in,
                              void* d_out, int out_size) {
    const float* x   = (const float*)d_in[0];  // (S, B, I)
    const float* h0  = (const float*)d_in[1];  // (1, B, H)
    const float* wih = (const float*)d_in[2];  // (3H, I)
    const float* whh = (const float*)d_in[3];  // (3H, H)
    const float* bih = (const float*)d_in[4];  // (3H,)
    const float* bhh = (const float*)d_in[5];  // (3H,)
    float* out = (float*)d_out;                // (1,S,B,H) then (1,B,H)

    dim3 ggrid(8, 1024);
    gx_gemm<<<ggrid, 256>>>(x, wih, bih, bhh);
    rec_kernel<<<128, 256>>>(h0, whh, out);
}

// round 8
// speedup vs baseline: 1.6560x; 1.1746x over previous
#include <cuda_runtime.h>
#include <cuda_bf16.h>
#include <cstddef>

#define S_LEN 2048
#define B_DIM 64
#define I_DIM 512
#define H_DIM 512
#define BH (B_DIM * H_DIM)          // 32768
#define GX_COLS 1024                // z gates [0,512), n gates [512,1024)

// Scratch: gx[t][b][g], g in 0..1023 maps to weight rows 512+g. 512 MB.
__device__ float g_gx[(size_t)S_LEN * B_DIM * GX_COLS];
// Sense-reversing group barrier state (8 groups). Returns to {0,0} after the
// even number (2048) of flips each launch -> replay-safe.
__device__ int g_cnt[8];
__device__ int g_sense[8];

typedef unsigned long long ull;

__device__ __forceinline__ ull fma2(ull a, ull b, ull c) {
    ull d;
    asm("fma.rn.f32x2 %0, %1, %2, %3;" : "=l"(d) : "l"(a), "l"(b), "l"(c));
    return d;
}
__device__ __forceinline__ float sum2(ull u) {
    float lo, hi;
    asm("mov.b64 {%0,%1}, %2;" : "=f"(lo), "=f"(hi) : "l"(u));
    return lo + hi;
}
__device__ __forceinline__ void st_rel(int* p, int v) {
    asm volatile("st.release.gpu.global.b32 [%0], %1;" :: "l"(p), "r"(v) : "memory");
}
__device__ __forceinline__ int ld_acq(const int* p) {
    int v;
    asm volatile("ld.acquire.gpu.global.b32 %0, [%1];" : "=r"(v) : "l"(p) : "memory");
    return v;
}
// Fast gates: MUFU-based, ~1e-7 abs error, saturate correctly at +-inf.
__device__ __forceinline__ float fsig(float x) {
    return __fdividef(1.0f, 1.0f + __expf(-x));
}
__device__ __forceinline__ float ftanh(float x) {
    return 1.0f - __fdividef(2.0f, __expf(2.0f * x) + 1.0f);
}

// ---------------------------------------------------------------------------
// Kernel 1: gx = x @ Wih[512:1536]^T + (bias_ih + bias_hh)[512:1536]
// M=131072, N=1024, K=512. BM=BN=128, BK=16, 256 threads, 8x8 f32x2 tile.
// (unchanged — proven R2..R6)
// ---------------------------------------------------------------------------
__global__ void __launch_bounds__(256, 1)
gx_gemm(const float* __restrict__ x, const float* __restrict__ wih,
        const float* __restrict__ bih, const float* __restrict__ bhh) {
    __shared__ ull As2[8 * 130];
    __shared__ ull Bs2[8 * 130];

    const int tid = threadIdx.x;
    const int tx = tid & 15;
    const int ty = tid >> 4;
    const int n0 = blockIdx.x * 128;
    const size_t m0 = (size_t)blockIdx.y * 128;
    const int r = tid >> 1;
    const int half = tid & 1;
    const int kp0 = half * 4;

    float bz[8];
#pragma unroll
    for (int j = 0; j < 8; j++) {
        int n = n0 + tx + 16 * j;
        bz[j] = bih[512 + n] + bhh[512 + n];
    }

    ull acc[8][8];
#pragma unroll
    for (int i = 0; i < 8; i++)
#pragma unroll
        for (int j = 0; j < 8; j++) acc[i][j] = 0ull;

    const float* arow = x + (m0 + r) * 512 + half * 8;
    const float* brow = wih + (size_t)(512 + n0 + r) * 512 + half * 8;

    ulonglong2 A0 = *(const ulonglong2*)(arow);
    ulonglong2 A1 = *(const ulonglong2*)(arow + 4);
    ulonglong2 B0 = *(const ulonglong2*)(brow);
    ulonglong2 B1 = *(const ulonglong2*)(brow + 4);

    for (int kt = 0; kt < 32; kt++) {
        As2[(kp0 + 0) * 130 + r] = A0.x;
        As2[(kp0 + 1) * 130 + r] = A0.y;
        As2[(kp0 + 2) * 130 + r] = A1.x;
        As2[(kp0 + 3) * 130 + r] = A1.y;
        Bs2[(kp0 + 0) * 130 + r] = B0.x;
        Bs2[(kp0 + 1) * 130 + r] = B0.y;
        Bs2[(kp0 + 2) * 130 + r] = B1.x;
        Bs2[(kp0 + 3) * 130 + r] = B1.y;
        __syncthreads();
        if (kt < 31) {
            int ko = (kt + 1) * 16;
            A0 = *(const ulonglong2*)(arow + ko);
            A1 = *(const ulonglong2*)(arow + ko + 4);
            B0 = *(const ulonglong2*)(brow + ko);
            B1 = *(const ulonglong2*)(brow + ko + 4);
        }
#pragma unroll
        for (int kp = 0; kp < 8; kp++) {
            ull av[8], bv[8];
            const ulonglong2* ap = (const ulonglong2*)&As2[kp * 130 + ty * 8];
#pragma unroll
            for (int i2 = 0; i2 < 4; i2++) {
                ulonglong2 t2 = ap[i2];
                av[i2 * 2] = t2.x;
                av[i2 * 2 + 1] = t2.y;
            }
#pragma unroll
            for (int j = 0; j < 8; j++) bv[j] = Bs2[kp * 130 + tx + 16 * j];
#pragma unroll
            for (int i = 0; i < 8; i++)
#pragma unroll
                for (int j = 0; j < 8; j++) acc[i][j] = fma2(av[i], bv[j], acc[i][j]);
        }
        __syncthreads();
    }

#pragma unroll
    for (int i = 0; i < 8; i++) {
        float* orow = g_gx + (m0 + ty * 8 + i) * (size_t)GX_COLS + n0 + tx;
#pragma unroll
        for (int j = 0; j < 8; j++) orow[16 * j] = sum2(acc[i][j]) + bz[j];
    }
}

// ---------------------------------------------------------------------------
// Kernel 2: recurrence — R6 structure, with the epilogue DISTRIBUTED.
// 128 CTAs = 8 groups x 16 CTAs; group g: batches 8g..8g+7; CTA c: h-dims
// [32c, 32c+32). 256 threads; thread (wid,lane): hdg = wid*2 + (lane>>4),
// kp = lane&15; owns rows {z0,z1,n0,n1} of hd pair {hd0+2hdg, +1} over k in
// [32kp, 32kp+32): 128 weight floats in registers, step-invariant.
// After each batch's 4-round butterfly, ALL 16 lanes of a half hold the
// identical full sums; lane kp==b captures batch b. After the b-loop, lanes
// kp<8 (16 per warp) each run ONE epilogue (batch kp, this half's hd pair):
// MUFU warp-inst drop 64 -> 8 per warp per step, STG 8 -> 1.
// ---------------------------------------------------------------------------
__global__ void __launch_bounds__(256, 1)
rec_kernel(const float* __restrict__ h0, const float* __restrict__ whh,
           float* __restrict__ out) {
    __shared__ float4 h_s4[8][8][17];   // [b][q][kp] swizzled, k=(kp*8+q)*4+e

    const int tid = threadIdx.x;
    const int bx = blockIdx.x;
    const int grp = bx >> 4;
    const int gb = grp * 8;
    const int hd0 = (bx & 15) * 32;
    const int lane = tid & 31;
    const int wid = tid >> 5;
    const int kp = lane & 15;
    const int h1 = lane >> 4;
    const int hdg = wid * 2 + h1;
    const int hdp = hd0 + hdg * 2;      // this thread's hd pair base
    const bool ep = (kp < 8);           // epilogue lane: handles batch eb
    const int eb = kp;
    const int k4h = hdp >> 2;           // h_old float4 slot for this hd pair

    // Step-invariant weights in registers (128 floats).
    ulonglong2 wz0[8], wz1[8], wn0[8], wn1[8];
    {
        const ulonglong2* pz0 = (const ulonglong2*)(whh + (size_t)(512 + hdp) * 512 + kp * 32);
        const ulonglong2* pz1 = (const ulonglong2*)(whh + (size_t)(513 + hdp) * 512 + kp * 32);
        const ulonglong2* pn0 = (const ulonglong2*)(whh + (size_t)(1024 + hdp) * 512 + kp * 32);
        const ulonglong2* pn1 = (const ulonglong2*)(whh + (size_t)(1025 + hdp) * 512 + kp * 32);
#pragma unroll
        for (int q = 0; q < 8; q++) {
            wz0[q] = pz0[q];
            wz1[q] = pz1[q];
            wn0[q] = pn0[q];
            wn1[q] = pn1[q];
        }
    }

    // Stage h(-1) = h_0 into swizzled SMEM.
    {
        int b = tid >> 5, rr = tid & 31;
        const float4* src = (const float4*)(h0 + (size_t)(gb + b) * 512);
#pragma unroll
        for (int j = 0; j < 4; j++) {
            int k4 = j * 32 + rr;
            h_s4[b][k4 & 7][k4 >> 3] = __ldcg(src + k4);
        }
    }
    __syncthreads();

    int sense = 0;

    for (int t = 0; t < S_LEN; t++) {
        // Distributed prefetch: each epilogue lane loads only its own cells.
        float2 pgz = make_float2(0.f, 0.f), pgn = make_float2(0.f, 0.f);
        if (ep) {
            const float* gxt = g_gx + (size_t)t * B_DIM * GX_COLS + (size_t)(gb + eb) * GX_COLS;
            pgz = __ldcg((const float2*)(gxt + hdp));
            pgn = __ldcg((const float2*)(gxt + 512 + hdp));
        }

        float mz0 = 0.f, mz1 = 0.f, mn0 = 0.f, mn1 = 0.f;
#pragma unroll
        for (int b = 0; b < 8; b++) {
            ull az0 = 0, az1 = 0, an0 = 0, an1 = 0;
#pragma unroll
            for (int q = 0; q < 8; q++) {
                ulonglong2 h2 = *(const ulonglong2*)&h_s4[b][q][kp];
                az0 = fma2(wz0[q].x, h2.x, az0);
                az0 = fma2(wz0[q].y, h2.y, az0);
                az1 = fma2(wz1[q].x, h2.x, az1);
                az1 = fma2(wz1[q].y, h2.y, az1);
                an0 = fma2(wn0[q].x, h2.x, an0);
                an0 = fma2(wn0[q].y, h2.y, an0);
                an1 = fma2(wn1[q].x, h2.x, an1);
                an1 = fma2(wn1[q].y, h2.y, an1);
            }
            float rz0 = sum2(az0), rz1 = sum2(az1);
            float rn0 = sum2(an0), rn1 = sum2(an1);
#pragma unroll
            for (int off = 1; off < 16; off <<= 1) {
                rz0 += __shfl_xor_sync(0xffffffffu, rz0, off);
                rz1 += __shfl_xor_sync(0xffffffffu, rz1, off);
                rn0 += __shfl_xor_sync(0xffffffffu, rn0, off);
                rn1 += __shfl_xor_sync(0xffffffffu, rn1, off);
            }
            // All 16 lanes of this half now hold identical sums; lane kp==b
            // keeps batch b's values for the distributed epilogue.
            if (kp == b) { mz0 = rz0; mz1 = rz1; mn0 = rn0; mn1 = rn1; }
        }

        // Distributed epilogue: lanes kp<8 each update (batch eb, hd pair).
        if (ep) {
            float4 ho4 = h_s4[eb][k4h & 7][k4h >> 3];
            float ho0 = (hdp & 2) ? ho4.z : ho4.x;
            float ho1 = (hdp & 2) ? ho4.w : ho4.y;
            float z0 = fsig(pgz.x + mz0);
            float z1 = fsig(pgz.y + mz1);
            float n0v = ftanh(pgn.x + mn0);
            float n1v = ftanh(pgn.y + mn1);
            float2 hv;
            hv.x = ho0 + z0 * (n0v - ho0);
            hv.y = ho1 + z1 * (n1v - ho1);
            float* dst = out + (size_t)t * BH + (size_t)(gb + eb) * 512 + hdp;
            *(float2*)dst = hv;
            if (t == S_LEN - 1) {
                float* dn = out + (size_t)S_LEN * BH + (size_t)(gb + eb) * 512 + hdp;
                *(float2*)dn = hv;
            }
        }

        // Group barrier. bar.sync orders all CTA threads' h stores before
        // tid0; tid0's gpu-scope fence + release publish them; pollers use
        // acquire so the post-barrier restage sees all h[t].
        __syncthreads();
        sense ^= 1;
        if (tid == 0) {
            asm volatile("fence.acq_rel.gpu;" ::: "memory");
            if (atomicAdd(&g_cnt[grp], 1) == 15) {
                g_cnt[grp] = 0;
                st_rel(&g_sense[grp], sense);
            } else {
                while (ld_acq(&g_sense[grp]) != sense) __nanosleep(32);
            }
        }
        __syncthreads();

        // Restage h[t] from out (L2) into swizzled SMEM.
        {
            int b = tid >> 5, rr = tid & 31;
            const float4* src = (const float4*)(out + (size_t)t * BH + (size_t)(gb + b) * 512);
#pragma unroll
            for (int j = 0; j < 4; j++) {
                int k4 = j * 32 + rr;
                h_s4[b][k4 & 7][k4 >> 3] = __ldcg(src + k4);
            }
        }
        __syncthreads();
    }
}

extern "C" void kernel_launch(void* const* d_in, const int* in_sizes, int n_in,
                              void* d_out, int out_size) {
    const float* x   = (const float*)d_in[0];  // (S, B, I)
    const float* h0  = (const float*)d_in[1];  // (1, B, H)
    const float* wih = (const float*)d_in[2];  // (3H, I)
    const float* whh = (const float*)d_in[3];  // (3H, H)
    const float* bih = (const float*)d_in[4];  // (3H,)
    const float* bhh = (const float*)d_in[5];  // (3H,)
    float* out = (float*)d_out;                // (1,S,B,H) then (1,B,H)

    dim3 ggrid(8, 1024);
    gx_gemm<<<ggrid, 256>>>(x, wih, bih, bhh);
    rec_kernel<<<128, 256>>>(h0, whh, out);
}